// round 15
// baseline (speedup 1.0000x reference)
#include <cuda_runtime.h>
#include <cuda_bf16.h>
#include <math.h>
#include <stdint.h>

#define E 128
#define H 8
#define L 2048
#define HE 1024
#define HEL (HE * L)
#define NITEMS 50000
#define WAMT 5
#define SCALE_F 0.08838834764831845f

__device__ __nv_bfloat16 g_Ih[L * E], g_Il[L * E];           // I [l][e]
__device__ __nv_bfloat16 g_Wh[3 * HE * E], g_Wl[3 * HE * E]; // W [z][he][k]
__device__ __nv_bfloat16 g_Qh[H * L * E], g_Ql[H * L * E];   // [h][l][e], pre-scaled
__device__ __nv_bfloat16 g_Kh[H * L * E], g_Kl[H * L * E];   // [h][l][e]
__device__ __nv_bfloat16 g_Vh[H * E * L], g_Vl[H * E * L];   // [h][e][l]
__device__ __nv_bfloat16 g_bh[L * HE], g_bl[L * HE];         // [l][he]
__device__ __nv_bfloat16 g_Ah[E * HE], g_Al[E * HE];         // [e_out][k]

__device__ __forceinline__ uint32_t smem_u32(const void* p) {
    return (uint32_t)__cvta_generic_to_shared(p);
}
__device__ __forceinline__ void ldsm4(uint32_t* r, uint32_t a) {
    asm volatile("ldmatrix.sync.aligned.m8n8.x4.shared.b16 {%0,%1,%2,%3}, [%4];"
                 : "=r"(r[0]), "=r"(r[1]), "=r"(r[2]), "=r"(r[3]) : "r"(a));
}
__device__ __forceinline__ void mma_bf16(float* c, const uint32_t* a, const uint32_t* b) {
    asm volatile("mma.sync.aligned.m16n8k16.row.col.f32.bf16.bf16.f32 "
                 "{%0,%1,%2,%3}, {%4,%5,%6,%7}, {%8,%9}, {%0,%1,%2,%3};"
                 : "+f"(c[0]), "+f"(c[1]), "+f"(c[2]), "+f"(c[3])
                 : "r"(a[0]), "r"(a[1]), "r"(a[2]), "r"(a[3]), "r"(b[0]), "r"(b[1]));
}
__device__ __forceinline__ void split2(float a, float b, __nv_bfloat162& h, __nv_bfloat162& l) {
    h = __floats2bfloat162_rn(a, b);
    float2 r = __bfloat1622float2(h);
    l = __floats2bfloat162_rn(a - r.x, b - r.y);
}
#define CPA16(dst, src) \
    asm volatile("cp.async.cg.shared.global [%0], [%1], 16;" :: "r"(dst), "l"(src) : "memory")
#define CPA_COMMIT() asm volatile("cp.async.commit_group;" ::: "memory")
#define CPA_WAIT(n)  asm volatile("cp.async.wait_group %0;" :: "n"(n) : "memory")

// ---------------------------------------------------------------------------
__global__ void build_I_kernel(const int* __restrict__ sq, const int* __restrict__ cq,
                               const float* __restrict__ ir, const float* __restrict__ wr,
                               const float* __restrict__ uir, float* __restrict__ out) {
    int idx = blockIdx.x * blockDim.x + threadIdx.x;   // idx = l*128 + e
    if (idx < E) out[idx] = uir[idx];
    if (idx >= E * L) return;
    int e = idx & 127, l = idx >> 7;
    float iq = ir[e * NITEMS + sq[l]];
    float val = iq + wr[e * WAMT + cq[l]];
    __nv_bfloat16 hv = __float2bfloat16(val);
    g_Ih[idx] = hv;
    g_Il[idx] = __float2bfloat16(val - __bfloat162float(hv));
    out[E * L + idx] = iq;
}

// Split Wq/Wk/Wv (z=0..2) and Head_agg (z=3) into bf16 hi/lo
__global__ void prep_WA_kernel(const float* __restrict__ Wq, const float* __restrict__ Wk,
                               const float* __restrict__ Wv, const float* __restrict__ A) {
    int idx = blockIdx.x * blockDim.x + threadIdx.x;   // 0..262143, 2 floats each
    int z = idx >> 16;
    int off = (idx & 65535) * 2;
    const float* S = (z == 0) ? Wq : (z == 1 ? Wk : (z == 2 ? Wv : A));
    __nv_bfloat16* Dh = (z < 3) ? (g_Wh + (size_t)z * (HE * E)) : g_Ah;
    __nv_bfloat16* Dl = (z < 3) ? (g_Wl + (size_t)z * (HE * E)) : g_Al;
    float2 f = *(const float2*)&S[off];
    __nv_bfloat162 hh, ll;
    split2(f.x, f.y, hh, ll);
    *(__nv_bfloat162*)&Dh[off] = hh;
    *(__nv_bfloat162*)&Dl[off] = ll;
}

// ---------------------------------------------------------------------------
// QKV projection via mma.sync. Grid (16,8,3). Per CTA: M=128 he, N=128 l, K=128.
// Warp grid 2m x 4n. cp.async one-shot tile loads.
// ---------------------------------------------------------------------------
#define QSTR 136
#define QA_H 0
#define QA_L 34816
#define QB_H 69632
#define QB_L 104448
#define QKV_SMEM 139264

__global__ __launch_bounds__(256) void gemm_qkv_tc() {
    extern __shared__ __align__(128) char smq[];
    const uint32_t sb = smem_u32(smq);
    const int t = threadIdx.x, w = t >> 5, ln = t & 31;
    const int z = blockIdx.z;
    const int bm = blockIdx.y * 128;   // he tile
    const int bn = blockIdx.x * 128;   // l tile
    const __nv_bfloat16* Wh = g_Wh + (size_t)z * (HE * E);
    const __nv_bfloat16* Wl = g_Wl + (size_t)z * (HE * E);

    // cp.async one-shot loads: A (W) + B (I), 128 rows x 16 chunks each, hi+lo
#pragma unroll
    for (int r = 0; r < 8; ++r) {
        int id = t + r * 256, row = id >> 4, c16 = id & 15;
        CPA16(sb + QA_H + row * 272 + c16 * 16,
              (const char*)(Wh + (size_t)(bm + row) * E) + c16 * 16);
        CPA16(sb + QA_L + row * 272 + c16 * 16,
              (const char*)(Wl + (size_t)(bm + row) * E) + c16 * 16);
        CPA16(sb + QB_H + row * 272 + c16 * 16,
              (const char*)(g_Ih + (size_t)(bn + row) * E) + c16 * 16);
        CPA16(sb + QB_L + row * 272 + c16 * 16,
              (const char*)(g_Il + (size_t)(bn + row) * E) + c16 * 16);
    }
    CPA_COMMIT();
    CPA_WAIT(0);
    __syncthreads();

    const int wm = w & 1;              // m-warp: 0..1 (m64 each)
    const int wn = w >> 1;             // n-warp: 0..3 (n32 each)
    const int mA = ln >> 3, g8 = ln & 7;
    const int aRowB = wm * 64 + g8 + (mA & 1) * 8;
    const int aCol  = (mA >> 1) * 8;
    const int bRowB = wn * 32 + g8 + (mA >> 1) * 8;
    const int bCol  = (mA & 1) * 8;

    float acc[16][4];
#pragma unroll
    for (int u = 0; u < 16; u++)
#pragma unroll
        for (int v = 0; v < 4; v++) acc[u][v] = 0.f;

#pragma unroll
    for (int ks = 0; ks < 8; ++ks) {
        int ko = ks * 16;
        uint32_t ah[4][4], al[4][4];
#pragma unroll
        for (int mt = 0; mt < 4; ++mt) {
            uint32_t aoff = (uint32_t)(((aRowB + mt * 16) * QSTR + ko + aCol) * 2);
            ldsm4(ah[mt], sb + QA_H + aoff);
            ldsm4(al[mt], sb + QA_L + aoff);
        }
#pragma unroll
        for (int nt = 0; nt < 2; ++nt) {
            uint32_t bh[4], bl[4];
            uint32_t boff = (uint32_t)(((bRowB + nt * 16) * QSTR + ko + bCol) * 2);
            ldsm4(bh, sb + QB_H + boff);
            ldsm4(bl, sb + QB_L + boff);
#pragma unroll
            for (int mt = 0; mt < 4; ++mt) {
                float* c0 = acc[mt * 4 + nt * 2];
                float* c1 = acc[mt * 4 + nt * 2 + 1];
                mma_bf16(c0, ah[mt], bh);
                mma_bf16(c0, ah[mt], bl);
                mma_bf16(c0, al[mt], bh);
                mma_bf16(c1, ah[mt], bh + 2);
                mma_bf16(c1, ah[mt], bl + 2);
                mma_bf16(c1, al[mt], bh + 2);
            }
        }
    }

    const int g = ln >> 2, q2 = (ln & 3) * 2;
    if (z == 2) {
        // V: direct store [he][l], n (=l) contiguous
#pragma unroll
        for (int mt = 0; mt < 4; ++mt) {
            const int row0 = bm + wm * 64 + mt * 16 + g;
#pragma unroll
            for (int nf = 0; nf < 4; ++nf) {
                const float* cc = acc[mt * 4 + nf];
                int col = bn + wn * 32 + nf * 8 + q2;
                __nv_bfloat162 h01, l01, h23, l23;
                split2(cc[0], cc[1], h01, l01);
                split2(cc[2], cc[3], h23, l23);
                *(__nv_bfloat162*)&g_Vh[(size_t)row0 * L + col] = h01;
                *(__nv_bfloat162*)&g_Vl[(size_t)row0 * L + col] = l01;
                *(__nv_bfloat162*)&g_Vh[(size_t)(row0 + 8) * L + col] = h23;
                *(__nv_bfloat162*)&g_Vl[(size_t)(row0 + 8) * L + col] = l23;
            }
        }
    } else {
        // Q/K: transpose via fp32 staging aliased onto B region, then [h][l][e]
        __syncthreads();
        float* st = (float*)(smq + QB_H);   // [128 l][132]
#pragma unroll
        for (int mt = 0; mt < 4; ++mt) {
            const int r0 = wm * 64 + mt * 16 + g;
#pragma unroll
            for (int nf = 0; nf < 4; ++nf) {
                const float* cc = acc[mt * 4 + nf];
                int lc = wn * 32 + nf * 8 + q2;
                st[lc * 132 + r0]           = cc[0];
                st[(lc + 1) * 132 + r0]     = cc[1];
                st[lc * 132 + r0 + 8]       = cc[2];
                st[(lc + 1) * 132 + r0 + 8] = cc[3];
            }
        }
        __syncthreads();
        const float s = (z == 0) ? SCALE_F : 1.0f;
        __nv_bfloat16* Dh = (z == 0) ? g_Qh : g_Kh;
        __nv_bfloat16* Dl = (z == 0) ? g_Ql : g_Kl;
        const int lrow = t >> 1, ec = (t & 1) * 64;
        const int h = bm >> 7;
        size_t base = ((size_t)h * L + bn + lrow) * E + ec;
#pragma unroll
        for (int i4 = 0; i4 < 16; ++i4) {
            float4 f = *(const float4*)&st[lrow * 132 + ec + i4 * 4];
            __nv_bfloat162 h01, l01, h23, l23;
            split2(f.x * s, f.y * s, h01, l01);
            split2(f.z * s, f.w * s, h23, l23);
            *(__nv_bfloat162*)&Dh[base + i4 * 4]     = h01;
            *(__nv_bfloat162*)&Dl[base + i4 * 4]     = l01;
            *(__nv_bfloat162*)&Dh[base + i4 * 4 + 2] = h23;
            *(__nv_bfloat162*)&Dl[base + i4 * 4 + 2] = l23;
        }
    }
}

// ---------------------------------------------------------------------------
// Flash attention, register-resident P (round-10, unchanged).
// ---------------------------------------------------------------------------
#define SQK 136
#define SV 72
#define S_QH 0
#define S_QL 17408
#define S_KV 34816
#define KSZ  17408
#define VSZ  18432
#define BUFSZ (2 * KSZ + 2 * VSZ)
#define S_XB (S_KV + BUFSZ)
#define ATTN_SMEM (S_KV + 2 * BUFSZ)

__device__ __forceinline__ void prefetch_kv(uint32_t sb, int buf,
                                            const __nv_bfloat16* Kh, const __nv_bfloat16* Kl,
                                            const __nv_bfloat16* Vh, const __nv_bfloat16* Vl,
                                            int ib, int t) {
    const uint32_t kb = sb + S_KV + buf * BUFSZ;
#pragma unroll
    for (int r = 0; r < 4; ++r) {
        int id = t + r * 256, row = id >> 4, c16 = id & 15;
        const char* sh = (const char*)(Kh + (size_t)(ib * 64 + row) * E) + c16 * 16;
        const char* sl = (const char*)(Kl + (size_t)(ib * 64 + row) * E) + c16 * 16;
        CPA16(kb + row * 272 + c16 * 16, sh);
        CPA16(kb + KSZ + row * 272 + c16 * 16, sl);
    }
    const uint32_t vb = kb + 2 * KSZ;
#pragma unroll
    for (int r = 0; r < 4; ++r) {
        int id = t + r * 256, row = id >> 3, c8 = id & 7;
        const char* sh = (const char*)(Vh + (size_t)row * L + ib * 64) + c8 * 16;
        const char* sl = (const char*)(Vl + (size_t)row * L + ib * 64) + c8 * 16;
        CPA16(vb + row * 144 + c8 * 16, sh);
        CPA16(vb + VSZ + row * 144 + c8 * 16, sl);
    }
    CPA_COMMIT();
}

__global__ __launch_bounds__(256, 1) void attn_kernel() {
    extern __shared__ __align__(128) char smc[];
    const uint32_t sb = smem_u32(smc);
    const int t = threadIdx.x, w = t >> 5, ln = t & 31;
    const int h = blockIdx.y, px = blockIdx.x;

    const __nv_bfloat16* Qh = g_Qh + (size_t)h * L * E;
    const __nv_bfloat16* Ql = g_Ql + (size_t)h * L * E;
    const __nv_bfloat16* Kh = g_Kh + (size_t)h * L * E;
    const __nv_bfloat16* Kl = g_Kl + (size_t)h * L * E;
    const __nv_bfloat16* Vh = g_Vh + (size_t)h * E * L;
    const __nv_bfloat16* Vl = g_Vl + (size_t)h * E * L;

    const int jw  = (w >> 1) * 16;
    const int ihw = (w & 1) * 32;
    const int g   = ln >> 2;
    const int q2  = (ln & 3) * 2;
    const int mA = ln >> 3, g8 = ln & 7;
    const int aRow = jw + g8 + (mA & 1) * 8;
    const int aCol = (mA >> 1) * 8;
    const int bRow = g8 + (mA >> 1) * 8;
    const int bCol = (mA & 1) * 8;

#pragma unroll 1
    for (int ts = 0; ts < 2; ++ts) {
        const int jt = ts ? px : (31 - px);
        const int qb = jt << 6;
        __syncthreads();

        prefetch_kv(sb, 0, Kh, Kl, Vh, Vl, 0, t);

#pragma unroll
        for (int r = 0; r < 4; ++r) {
            int id = t + r * 256, row = id >> 4, c16 = id & 15;
            *(uint4*)(smc + S_QH + row * 272 + c16 * 16) =
                *((const uint4*)(Qh + (size_t)(qb + row) * E) + c16);
            *(uint4*)(smc + S_QL + row * 272 + c16 * 16) =
                *((const uint4*)(Ql + (size_t)(qb + row) * E) + c16);
        }

        float bacc[16][4];
#pragma unroll
        for (int u = 0; u < 16; u++)
#pragma unroll
            for (int v = 0; v < 4; v++) bacc[u][v] = 0.f;
        float lsum0 = 0.f, lsum1 = 0.f;
        const int jg0 = qb + jw + g, jg1 = jg0 + 8;

#pragma unroll 1
        for (int ib = 0; ib <= jt; ++ib) {
            __syncthreads();
            if (ib < jt) {
                prefetch_kv(sb, (ib + 1) & 1, Kh, Kl, Vh, Vl, ib + 1, t);
                CPA_WAIT(1);
            } else {
                CPA_WAIT(0);
            }
            __syncthreads();

            const uint32_t kH = sb + S_KV + (ib & 1) * BUFSZ;
            const uint32_t kL = kH + KSZ;
            const uint32_t vH = kH + 2 * KSZ;
            const uint32_t vL = vH + VSZ;

            float sacc[4][4];
#pragma unroll
            for (int u = 0; u < 4; u++)
#pragma unroll
                for (int v = 0; v < 4; v++) sacc[u][v] = 0.f;
#pragma unroll
            for (int ks = 0; ks < 8; ++ks) {
                int e0 = ks * 16;
                uint32_t ah[4], al[4];
                ldsm4(ah, sb + S_QH + (uint32_t)((aRow * SQK + e0 + aCol) * 2));
                ldsm4(al, sb + S_QL + (uint32_t)((aRow * SQK + e0 + aCol) * 2));
#pragma unroll
                for (int it = 0; it < 2; ++it) {
                    uint32_t bh[4], bl[4];
                    uint32_t boff = (uint32_t)(((ihw + it * 16 + bRow) * SQK + e0 + bCol) * 2);
                    ldsm4(bh, kH + boff);
                    ldsm4(bl, kL + boff);
                    mma_bf16(sacc[it * 2], ah, bh);
                    mma_bf16(sacc[it * 2], ah, bl);
                    mma_bf16(sacc[it * 2], al, bh);
                    mma_bf16(sacc[it * 2 + 1], ah, bh + 2);
                    mma_bf16(sacc[it * 2 + 1], ah, bl + 2);
                    mma_bf16(sacc[it * 2 + 1], al, bh + 2);
                }
            }

            uint32_t aPh[2][4], aPl[2][4];
#pragma unroll
            for (int nf = 0; nf < 4; ++nf) {
                int ig = ib * 64 + ihw + nf * 8 + q2;
                float p0 = (ig     <= jg0) ? __expf(sacc[nf][0]) : 0.f;
                float p1 = (ig + 1 <= jg0) ? __expf(sacc[nf][1]) : 0.f;
                float p2 = (ig     <= jg1) ? __expf(sacc[nf][2]) : 0.f;
                float p3 = (ig + 1 <= jg1) ? __expf(sacc[nf][3]) : 0.f;
                lsum0 += p0 + p1;
                lsum1 += p2 + p3;
                __nv_bfloat162 h01, l01, h23, l23;
                split2(p0, p1, h01, l01);
                split2(p2, p3, h23, l23);
                int kb = nf >> 1, sub = (nf & 1) * 2;
                aPh[kb][sub]     = *(uint32_t*)&h01;
                aPh[kb][sub + 1] = *(uint32_t*)&h23;
                aPl[kb][sub]     = *(uint32_t*)&l01;
                aPl[kb][sub + 1] = *(uint32_t*)&l23;
            }

#pragma unroll
            for (int kb = 0; kb < 2; ++kb) {
#pragma unroll
                for (int ef = 0; ef < 8; ++ef) {
                    uint32_t bh[4], bl[4];
                    uint32_t boff = (uint32_t)(((ef * 16 + bRow) * SV +
                                                ihw + kb * 16 + bCol) * 2);
                    ldsm4(bh, vH + boff);
                    ldsm4(bl, vL + boff);
                    mma_bf16(bacc[ef * 2], aPh[kb], bh);
                    mma_bf16(bacc[ef * 2], aPh[kb], bl);
                    mma_bf16(bacc[ef * 2], aPl[kb], bh);
                    mma_bf16(bacc[ef * 2 + 1], aPh[kb], bh + 2);
                    mma_bf16(bacc[ef * 2 + 1], aPh[kb], bl + 2);
                    mma_bf16(bacc[ef * 2 + 1], aPl[kb], bh + 2);
                }
            }
        }

        __syncthreads();
        float* XB = (float*)(smc + S_XB);
        const int xbase = ((w >> 1) * 32 + ln) * 68;
        if (w & 1) {
#pragma unroll
            for (int nf = 0; nf < 16; ++nf) {
                XB[xbase + nf * 4 + 0] = bacc[nf][0];
                XB[xbase + nf * 4 + 1] = bacc[nf][1];
                XB[xbase + nf * 4 + 2] = bacc[nf][2];
                XB[xbase + nf * 4 + 3] = bacc[nf][3];
            }
            XB[xbase + 64] = lsum0;
            XB[xbase + 65] = lsum1;
        }
        __syncthreads();
        if (!(w & 1)) {
#pragma unroll
            for (int nf = 0; nf < 16; ++nf) {
                bacc[nf][0] += XB[xbase + nf * 4 + 0];
                bacc[nf][1] += XB[xbase + nf * 4 + 1];
                bacc[nf][2] += XB[xbase + nf * 4 + 2];
                bacc[nf][3] += XB[xbase + nf * 4 + 3];
            }
            lsum0 += XB[xbase + 64];
            lsum1 += XB[xbase + 65];
            lsum0 += __shfl_xor_sync(0xffffffffu, lsum0, 1);
            lsum0 += __shfl_xor_sync(0xffffffffu, lsum0, 2);
            lsum1 += __shfl_xor_sync(0xffffffffu, lsum1, 1);
            lsum1 += __shfl_xor_sync(0xffffffffu, lsum1, 2);
            float li0 = 1.0f / lsum0, li1 = 1.0f / lsum1;
            const int j0 = qb + jw + g;
#pragma unroll
            for (int nf = 0; nf < 16; ++nf) {
                int e0 = h * E + nf * 8 + q2;
                __nv_bfloat162 h01, l01, h23, l23;
                split2(bacc[nf][0] * li0, bacc[nf][1] * li0, h01, l01);
                split2(bacc[nf][2] * li1, bacc[nf][3] * li1, h23, l23);
                size_t b0 = (size_t)j0 * HE + e0;
                size_t b1 = (size_t)(j0 + 8) * HE + e0;
                *(__nv_bfloat162*)&g_bh[b0] = h01;
                *(__nv_bfloat162*)&g_bl[b0] = l01;
                *(__nv_bfloat162*)&g_bh[b1] = h23;
                *(__nv_bfloat162*)&g_bl[b1] = l23;
            }
        }
    }
}

// ---------------------------------------------------------------------------
// gemm_out via mma.sync, cp.async double-buffered k-chunks.
// Per-buffer: Ah 18432 + Al 18432 + Bh 4608 + Bl 4608 = 46080; x2 = 92160.
// ---------------------------------------------------------------------------
#define OBUF 46080
#define O_AH 0
#define O_AL 18432
#define O_BH 36864
#define O_BL 41472
#define OUT_SMEM 92160

__device__ __forceinline__ void prefetch_out(uint32_t sb, int buf, int k0, int bn, int t) {
    const uint32_t ob = sb + buf * OBUF;
#pragma unroll
    for (int r = 0; r < 4; ++r) {
        int id = t + r * 256, row = id >> 3, c8 = id & 7;
        CPA16(ob + O_AH + row * 144 + c8 * 16,
              (const char*)(g_Ah + (size_t)row * HE + k0) + c8 * 16);
        CPA16(ob + O_AL + row * 144 + c8 * 16,
              (const char*)(g_Al + (size_t)row * HE + k0) + c8 * 16);
    }
    {
        int row = t >> 3, c8 = t & 7;
        CPA16(ob + O_BH + row * 144 + c8 * 16,
              (const char*)(g_bh + (size_t)(bn + row) * HE + k0) + c8 * 16);
        CPA16(ob + O_BL + row * 144 + c8 * 16,
              (const char*)(g_bl + (size_t)(bn + row) * HE + k0) + c8 * 16);
    }
    CPA_COMMIT();
}

__global__ __launch_bounds__(256) void gemm_out_tc(float* __restrict__ out) {
    extern __shared__ __align__(128) char sm2[];
    const uint32_t sb = smem_u32(sm2);
    const int t = threadIdx.x, w = t >> 5, ln = t & 31;
    const int bn = blockIdx.x * 32;
    const int mbase = w * 16;
    const int mA = ln >> 3, g8 = ln & 7;
    const int aRow = mbase + g8 + (mA & 1) * 8;
    const int aCol = (mA >> 1) * 8;
    const int bRow = g8 + (mA >> 1) * 8;
    const int bCol = (mA & 1) * 8;

    float acc[4][4];
#pragma unroll
    for (int u = 0; u < 4; u++)
#pragma unroll
        for (int v = 0; v < 4; v++) acc[u][v] = 0.f;

    prefetch_out(sb, 0, 0, bn, t);

    for (int kc = 0; kc < 16; ++kc) {
        __syncthreads();   // prior compute done -> next buffer free
        if (kc < 15) {
            prefetch_out(sb, (kc + 1) & 1, (kc + 1) * 64, bn, t);
            CPA_WAIT(1);
        } else {
            CPA_WAIT(0);
        }
        __syncthreads();   // current buffer visible

        const uint32_t ob = sb + (kc & 1) * OBUF;
#pragma unroll
        for (int kf = 0; kf < 4; ++kf) {
            int ko = kf * 16;
            uint32_t ah[4], al[4];
            uint32_t aoff = (uint32_t)((aRow * 72 + ko + aCol) * 2);
            ldsm4(ah, ob + O_AH + aoff);
            ldsm4(al, ob + O_AL + aoff);
#pragma unroll
            for (int np = 0; np < 2; ++np) {
                int n16 = np * 16;
                uint32_t bh[4], bl[4];
                uint32_t boff = (uint32_t)(((n16 + bRow) * 72 + ko + bCol) * 2);
                ldsm4(bh, ob + O_BH + boff);
                ldsm4(bl, ob + O_BL + boff);
                mma_bf16(acc[np * 2], ah, bh);
                mma_bf16(acc[np * 2], ah, bl);
                mma_bf16(acc[np * 2], al, bh);
                mma_bf16(acc[np * 2 + 1], ah, bh + 2);
                mma_bf16(acc[np * 2 + 1], ah, bl + 2);
                mma_bf16(acc[np * 2 + 1], al, bh + 2);
            }
        }
    }
    const int r0 = mbase + (ln >> 2);
#pragma unroll
    for (int nf = 0; nf < 4; ++nf) {
        int j0 = bn + nf * 8 + (ln & 3) * 2;
        int ee[4] = {r0, r0, r0 + 8, r0 + 8};
        int jj[4] = {j0, j0 + 1, j0, j0 + 1};
#pragma unroll
        for (int q = 0; q < 4; ++q) {
            int dst = (jj[q] < L - 1) ? (E + jj[q] * E + ee[q]) : (2 * E * L + ee[q]);
            out[dst] = acc[nf][q];
        }
    }
}

// ---------------------------------------------------------------------------
extern "C" void kernel_launch(void* const* d_in, const int* in_sizes, int n_in,
                              void* d_out, int out_size) {
    const int* sq = (const int*)d_in[0];
    const int* cq = (const int*)d_in[1];
    const float* ir = (const float*)d_in[2];
    const float* uir = (const float*)d_in[3];
    const float* wr = (const float*)d_in[4];
    const float* Wq = (const float*)d_in[5];
    const float* Wk = (const float*)d_in[6];
    const float* Wv = (const float*)d_in[7];
    const float* Hagg = (const float*)d_in[8];
    float* out = (float*)d_out;
    cudaFuncSetAttribute(attn_kernel, cudaFuncAttributeMaxDynamicSharedMemorySize, ATTN_SMEM);
    cudaFuncSetAttribute(gemm_qkv_tc, cudaFuncAttributeMaxDynamicSharedMemorySize, QKV_SMEM);
    cudaFuncSetAttribute(gemm_out_tc, cudaFuncAttributeMaxDynamicSharedMemorySize, OUT_SMEM);
    build_I_kernel<<<(E * L) / 256, 256>>>(sq, cq, ir, wr, uir, out);
    prep_WA_kernel<<<1024, 256>>>(Wq, Wk, Wv, Hagg);
    gemm_qkv_tc<<<dim3(16, 8, 3), 256, QKV_SMEM>>>();
    attn_kernel<<<dim3(16, H), 256, ATTN_SMEM>>>();
    gemm_out_tc<<<64, 256, OUT_SMEM>>>(out);
}

// round 16
// speedup vs baseline: 1.0187x; 1.0187x over previous
#include <cuda_runtime.h>
#include <cuda_bf16.h>
#include <math.h>
#include <stdint.h>

#define E 128
#define H 8
#define L 2048
#define HE 1024
#define HEL (HE * L)
#define NITEMS 50000
#define WAMT 5
#define SCALE_F 0.08838834764831845f

__device__ __nv_bfloat16 g_Ih[L * E], g_Il[L * E];           // I [l][e]
__device__ __nv_bfloat16 g_Wh[3 * HE * E], g_Wl[3 * HE * E]; // W [z][he][k]
__device__ __nv_bfloat16 g_Qh[H * L * E], g_Ql[H * L * E];   // [h][l][e], pre-scaled
__device__ __nv_bfloat16 g_Kh[H * L * E], g_Kl[H * L * E];   // [h][l][e]
__device__ __nv_bfloat16 g_Vh[H * E * L], g_Vl[H * E * L];   // [h][e][l]
__device__ __nv_bfloat16 g_bh[L * HE], g_bl[L * HE];         // [l][he]
__device__ __nv_bfloat16 g_Ah[E * HE], g_Al[E * HE];         // [e_out][k]

__device__ __forceinline__ uint32_t smem_u32(const void* p) {
    return (uint32_t)__cvta_generic_to_shared(p);
}
__device__ __forceinline__ void ldsm4(uint32_t* r, uint32_t a) {
    asm volatile("ldmatrix.sync.aligned.m8n8.x4.shared.b16 {%0,%1,%2,%3}, [%4];"
                 : "=r"(r[0]), "=r"(r[1]), "=r"(r[2]), "=r"(r[3]) : "r"(a));
}
__device__ __forceinline__ void mma_bf16(float* c, const uint32_t* a, const uint32_t* b) {
    asm volatile("mma.sync.aligned.m16n8k16.row.col.f32.bf16.bf16.f32 "
                 "{%0,%1,%2,%3}, {%4,%5,%6,%7}, {%8,%9}, {%0,%1,%2,%3};"
                 : "+f"(c[0]), "+f"(c[1]), "+f"(c[2]), "+f"(c[3])
                 : "r"(a[0]), "r"(a[1]), "r"(a[2]), "r"(a[3]), "r"(b[0]), "r"(b[1]));
}
__device__ __forceinline__ void split2(float a, float b, __nv_bfloat162& h, __nv_bfloat162& l) {
    h = __floats2bfloat162_rn(a, b);
    float2 r = __bfloat1622float2(h);
    l = __floats2bfloat162_rn(a - r.x, b - r.y);
}
#define CPA16(dst, src) \
    asm volatile("cp.async.cg.shared.global [%0], [%1], 16;" :: "r"(dst), "l"(src) : "memory")
#define CPA_COMMIT() asm volatile("cp.async.commit_group;" ::: "memory")
#define CPA_WAIT(n)  asm volatile("cp.async.wait_group %0;" :: "n"(n) : "memory")

// ---------------------------------------------------------------------------
__global__ void build_I_kernel(const int* __restrict__ sq, const int* __restrict__ cq,
                               const float* __restrict__ ir, const float* __restrict__ wr,
                               const float* __restrict__ uir, float* __restrict__ out) {
    int idx = blockIdx.x * blockDim.x + threadIdx.x;   // idx = l*128 + e
    if (idx < E) out[idx] = uir[idx];
    if (idx >= E * L) return;
    int e = idx & 127, l = idx >> 7;
    float iq = ir[e * NITEMS + sq[l]];
    float val = iq + wr[e * WAMT + cq[l]];
    __nv_bfloat16 hv = __float2bfloat16(val);
    g_Ih[idx] = hv;
    g_Il[idx] = __float2bfloat16(val - __bfloat162float(hv));
    out[E * L + idx] = iq;
}

// Split Wq/Wk/Wv (z=0..2) and Head_agg (z=3) into bf16 hi/lo
__global__ void prep_WA_kernel(const float* __restrict__ Wq, const float* __restrict__ Wk,
                               const float* __restrict__ Wv, const float* __restrict__ A) {
    int idx = blockIdx.x * blockDim.x + threadIdx.x;   // 0..262143, 2 floats each
    int z = idx >> 16;
    int off = (idx & 65535) * 2;
    const float* S = (z == 0) ? Wq : (z == 1 ? Wk : (z == 2 ? Wv : A));
    __nv_bfloat16* Dh = (z < 3) ? (g_Wh + (size_t)z * (HE * E)) : g_Ah;
    __nv_bfloat16* Dl = (z < 3) ? (g_Wl + (size_t)z * (HE * E)) : g_Al;
    float2 f = *(const float2*)&S[off];
    __nv_bfloat162 hh, ll;
    split2(f.x, f.y, hh, ll);
    *(__nv_bfloat162*)&Dh[off] = hh;
    *(__nv_bfloat162*)&Dl[off] = ll;
}

// ---------------------------------------------------------------------------
// QKV projection via mma.sync. Grid (16,8,3). Per CTA: M=128 he, N=128 l, K=128.
// Warp grid 2m x 4n. cp.async one-shot tile loads.
// ---------------------------------------------------------------------------
#define QSTR 136
#define QA_H 0
#define QA_L 34816
#define QB_H 69632
#define QB_L 104448
#define QKV_SMEM 139264

__global__ __launch_bounds__(256) void gemm_qkv_tc() {
    extern __shared__ __align__(128) char smq[];
    const uint32_t sb = smem_u32(smq);
    const int t = threadIdx.x, w = t >> 5, ln = t & 31;
    const int z = blockIdx.z;
    const int bm = blockIdx.y * 128;   // he tile
    const int bn = blockIdx.x * 128;   // l tile
    const __nv_bfloat16* Wh = g_Wh + (size_t)z * (HE * E);
    const __nv_bfloat16* Wl = g_Wl + (size_t)z * (HE * E);

    // cp.async one-shot loads: A (W) + B (I), 128 rows x 16 chunks each, hi+lo
#pragma unroll
    for (int r = 0; r < 8; ++r) {
        int id = t + r * 256, row = id >> 4, c16 = id & 15;
        CPA16(sb + QA_H + row * 272 + c16 * 16,
              (const char*)(Wh + (size_t)(bm + row) * E) + c16 * 16);
        CPA16(sb + QA_L + row * 272 + c16 * 16,
              (const char*)(Wl + (size_t)(bm + row) * E) + c16 * 16);
        CPA16(sb + QB_H + row * 272 + c16 * 16,
              (const char*)(g_Ih + (size_t)(bn + row) * E) + c16 * 16);
        CPA16(sb + QB_L + row * 272 + c16 * 16,
              (const char*)(g_Il + (size_t)(bn + row) * E) + c16 * 16);
    }
    CPA_COMMIT();
    CPA_WAIT(0);
    __syncthreads();

    const int wm = w & 1;              // m-warp: 0..1 (m64 each)
    const int wn = w >> 1;             // n-warp: 0..3 (n32 each)
    const int mA = ln >> 3, g8 = ln & 7;
    const int aRowB = wm * 64 + g8 + (mA & 1) * 8;
    const int aCol  = (mA >> 1) * 8;
    const int bRowB = wn * 32 + g8 + (mA >> 1) * 8;
    const int bCol  = (mA & 1) * 8;

    float acc[16][4];
#pragma unroll
    for (int u = 0; u < 16; u++)
#pragma unroll
        for (int v = 0; v < 4; v++) acc[u][v] = 0.f;

#pragma unroll
    for (int ks = 0; ks < 8; ++ks) {
        int ko = ks * 16;
        uint32_t ah[4][4], al[4][4];
#pragma unroll
        for (int mt = 0; mt < 4; ++mt) {
            uint32_t aoff = (uint32_t)(((aRowB + mt * 16) * QSTR + ko + aCol) * 2);
            ldsm4(ah[mt], sb + QA_H + aoff);
            ldsm4(al[mt], sb + QA_L + aoff);
        }
#pragma unroll
        for (int nt = 0; nt < 2; ++nt) {
            uint32_t bh[4], bl[4];
            uint32_t boff = (uint32_t)(((bRowB + nt * 16) * QSTR + ko + bCol) * 2);
            ldsm4(bh, sb + QB_H + boff);
            ldsm4(bl, sb + QB_L + boff);
#pragma unroll
            for (int mt = 0; mt < 4; ++mt) {
                float* c0 = acc[mt * 4 + nt * 2];
                float* c1 = acc[mt * 4 + nt * 2 + 1];
                mma_bf16(c0, ah[mt], bh);
                mma_bf16(c0, ah[mt], bl);
                mma_bf16(c0, al[mt], bh);
                mma_bf16(c1, ah[mt], bh + 2);
                mma_bf16(c1, ah[mt], bl + 2);
                mma_bf16(c1, al[mt], bh + 2);
            }
        }
    }

    const int g = ln >> 2, q2 = (ln & 3) * 2;
    if (z == 2) {
        // V: direct store [he][l], n (=l) contiguous
#pragma unroll
        for (int mt = 0; mt < 4; ++mt) {
            const int row0 = bm + wm * 64 + mt * 16 + g;
#pragma unroll
            for (int nf = 0; nf < 4; ++nf) {
                const float* cc = acc[mt * 4 + nf];
                int col = bn + wn * 32 + nf * 8 + q2;
                __nv_bfloat162 h01, l01, h23, l23;
                split2(cc[0], cc[1], h01, l01);
                split2(cc[2], cc[3], h23, l23);
                *(__nv_bfloat162*)&g_Vh[(size_t)row0 * L + col] = h01;
                *(__nv_bfloat162*)&g_Vl[(size_t)row0 * L + col] = l01;
                *(__nv_bfloat162*)&g_Vh[(size_t)(row0 + 8) * L + col] = h23;
                *(__nv_bfloat162*)&g_Vl[(size_t)(row0 + 8) * L + col] = l23;
            }
        }
    } else {
        // Q/K: transpose via fp32 staging aliased onto B region, then [h][l][e]
        __syncthreads();
        float* st = (float*)(smq + QB_H);   // [128 l][132]
#pragma unroll
        for (int mt = 0; mt < 4; ++mt) {
            const int r0 = wm * 64 + mt * 16 + g;
#pragma unroll
            for (int nf = 0; nf < 4; ++nf) {
                const float* cc = acc[mt * 4 + nf];
                int lc = wn * 32 + nf * 8 + q2;
                st[lc * 132 + r0]           = cc[0];
                st[(lc + 1) * 132 + r0]     = cc[1];
                st[lc * 132 + r0 + 8]       = cc[2];
                st[(lc + 1) * 132 + r0 + 8] = cc[3];
            }
        }
        __syncthreads();
        const float s = (z == 0) ? SCALE_F : 1.0f;
        __nv_bfloat16* Dh = (z == 0) ? g_Qh : g_Kh;
        __nv_bfloat16* Dl = (z == 0) ? g_Ql : g_Kl;
        const int lrow = t >> 1, ec = (t & 1) * 64;
        const int h = bm >> 7;
        size_t base = ((size_t)h * L + bn + lrow) * E + ec;
#pragma unroll
        for (int i4 = 0; i4 < 16; ++i4) {
            float4 f = *(const float4*)&st[lrow * 132 + ec + i4 * 4];
            __nv_bfloat162 h01, l01, h23, l23;
            split2(f.x * s, f.y * s, h01, l01);
            split2(f.z * s, f.w * s, h23, l23);
            *(__nv_bfloat162*)&Dh[base + i4 * 4]     = h01;
            *(__nv_bfloat162*)&Dl[base + i4 * 4]     = l01;
            *(__nv_bfloat162*)&Dh[base + i4 * 4 + 2] = h23;
            *(__nv_bfloat162*)&Dl[base + i4 * 4 + 2] = l23;
        }
    }
}

// ---------------------------------------------------------------------------
// Flash attention, register-resident P (round-10, unchanged).
// ---------------------------------------------------------------------------
#define SQK 136
#define SV 72
#define S_QH 0
#define S_QL 17408
#define S_KV 34816
#define KSZ  17408
#define VSZ  18432
#define BUFSZ (2 * KSZ + 2 * VSZ)
#define S_XB (S_KV + BUFSZ)
#define ATTN_SMEM (S_KV + 2 * BUFSZ)

__device__ __forceinline__ void prefetch_kv(uint32_t sb, int buf,
                                            const __nv_bfloat16* Kh, const __nv_bfloat16* Kl,
                                            const __nv_bfloat16* Vh, const __nv_bfloat16* Vl,
                                            int ib, int t) {
    const uint32_t kb = sb + S_KV + buf * BUFSZ;
#pragma unroll
    for (int r = 0; r < 4; ++r) {
        int id = t + r * 256, row = id >> 4, c16 = id & 15;
        const char* sh = (const char*)(Kh + (size_t)(ib * 64 + row) * E) + c16 * 16;
        const char* sl = (const char*)(Kl + (size_t)(ib * 64 + row) * E) + c16 * 16;
        CPA16(kb + row * 272 + c16 * 16, sh);
        CPA16(kb + KSZ + row * 272 + c16 * 16, sl);
    }
    const uint32_t vb = kb + 2 * KSZ;
#pragma unroll
    for (int r = 0; r < 4; ++r) {
        int id = t + r * 256, row = id >> 3, c8 = id & 7;
        const char* sh = (const char*)(Vh + (size_t)row * L + ib * 64) + c8 * 16;
        const char* sl = (const char*)(Vl + (size_t)row * L + ib * 64) + c8 * 16;
        CPA16(vb + row * 144 + c8 * 16, sh);
        CPA16(vb + VSZ + row * 144 + c8 * 16, sl);
    }
    CPA_COMMIT();
}

__global__ __launch_bounds__(256, 1) void attn_kernel() {
    extern __shared__ __align__(128) char smc[];
    const uint32_t sb = smem_u32(smc);
    const int t = threadIdx.x, w = t >> 5, ln = t & 31;
    const int h = blockIdx.y, px = blockIdx.x;

    const __nv_bfloat16* Qh = g_Qh + (size_t)h * L * E;
    const __nv_bfloat16* Ql = g_Ql + (size_t)h * L * E;
    const __nv_bfloat16* Kh = g_Kh + (size_t)h * L * E;
    const __nv_bfloat16* Kl = g_Kl + (size_t)h * L * E;
    const __nv_bfloat16* Vh = g_Vh + (size_t)h * E * L;
    const __nv_bfloat16* Vl = g_Vl + (size_t)h * E * L;

    const int jw  = (w >> 1) * 16;
    const int ihw = (w & 1) * 32;
    const int g   = ln >> 2;
    const int q2  = (ln & 3) * 2;
    const int mA = ln >> 3, g8 = ln & 7;
    const int aRow = jw + g8 + (mA & 1) * 8;
    const int aCol = (mA >> 1) * 8;
    const int bRow = g8 + (mA >> 1) * 8;
    const int bCol = (mA & 1) * 8;

#pragma unroll 1
    for (int ts = 0; ts < 2; ++ts) {
        const int jt = ts ? px : (31 - px);
        const int qb = jt << 6;
        __syncthreads();

        prefetch_kv(sb, 0, Kh, Kl, Vh, Vl, 0, t);

#pragma unroll
        for (int r = 0; r < 4; ++r) {
            int id = t + r * 256, row = id >> 4, c16 = id & 15;
            *(uint4*)(smc + S_QH + row * 272 + c16 * 16) =
                *((const uint4*)(Qh + (size_t)(qb + row) * E) + c16);
            *(uint4*)(smc + S_QL + row * 272 + c16 * 16) =
                *((const uint4*)(Ql + (size_t)(qb + row) * E) + c16);
        }

        float bacc[16][4];
#pragma unroll
        for (int u = 0; u < 16; u++)
#pragma unroll
            for (int v = 0; v < 4; v++) bacc[u][v] = 0.f;
        float lsum0 = 0.f, lsum1 = 0.f;
        const int jg0 = qb + jw + g, jg1 = jg0 + 8;

#pragma unroll 1
        for (int ib = 0; ib <= jt; ++ib) {
            __syncthreads();
            if (ib < jt) {
                prefetch_kv(sb, (ib + 1) & 1, Kh, Kl, Vh, Vl, ib + 1, t);
                CPA_WAIT(1);
            } else {
                CPA_WAIT(0);
            }
            __syncthreads();

            const uint32_t kH = sb + S_KV + (ib & 1) * BUFSZ;
            const uint32_t kL = kH + KSZ;
            const uint32_t vH = kH + 2 * KSZ;
            const uint32_t vL = vH + VSZ;

            float sacc[4][4];
#pragma unroll
            for (int u = 0; u < 4; u++)
#pragma unroll
                for (int v = 0; v < 4; v++) sacc[u][v] = 0.f;
#pragma unroll
            for (int ks = 0; ks < 8; ++ks) {
                int e0 = ks * 16;
                uint32_t ah[4], al[4];
                ldsm4(ah, sb + S_QH + (uint32_t)((aRow * SQK + e0 + aCol) * 2));
                ldsm4(al, sb + S_QL + (uint32_t)((aRow * SQK + e0 + aCol) * 2));
#pragma unroll
                for (int it = 0; it < 2; ++it) {
                    uint32_t bh[4], bl[4];
                    uint32_t boff = (uint32_t)(((ihw + it * 16 + bRow) * SQK + e0 + bCol) * 2);
                    ldsm4(bh, kH + boff);
                    ldsm4(bl, kL + boff);
                    mma_bf16(sacc[it * 2], ah, bh);
                    mma_bf16(sacc[it * 2], ah, bl);
                    mma_bf16(sacc[it * 2], al, bh);
                    mma_bf16(sacc[it * 2 + 1], ah, bh + 2);
                    mma_bf16(sacc[it * 2 + 1], ah, bl + 2);
                    mma_bf16(sacc[it * 2 + 1], al, bh + 2);
                }
            }

            uint32_t aPh[2][4], aPl[2][4];
#pragma unroll
            for (int nf = 0; nf < 4; ++nf) {
                int ig = ib * 64 + ihw + nf * 8 + q2;
                float p0 = (ig     <= jg0) ? __expf(sacc[nf][0]) : 0.f;
                float p1 = (ig + 1 <= jg0) ? __expf(sacc[nf][1]) : 0.f;
                float p2 = (ig     <= jg1) ? __expf(sacc[nf][2]) : 0.f;
                float p3 = (ig + 1 <= jg1) ? __expf(sacc[nf][3]) : 0.f;
                lsum0 += p0 + p1;
                lsum1 += p2 + p3;
                __nv_bfloat162 h01, l01, h23, l23;
                split2(p0, p1, h01, l01);
                split2(p2, p3, h23, l23);
                int kb = nf >> 1, sub = (nf & 1) * 2;
                aPh[kb][sub]     = *(uint32_t*)&h01;
                aPh[kb][sub + 1] = *(uint32_t*)&h23;
                aPl[kb][sub]     = *(uint32_t*)&l01;
                aPl[kb][sub + 1] = *(uint32_t*)&l23;
            }

#pragma unroll
            for (int kb = 0; kb < 2; ++kb) {
#pragma unroll
                for (int ef = 0; ef < 8; ++ef) {
                    uint32_t bh[4], bl[4];
                    uint32_t boff = (uint32_t)(((ef * 16 + bRow) * SV +
                                                ihw + kb * 16 + bCol) * 2);
                    ldsm4(bh, vH + boff);
                    ldsm4(bl, vL + boff);
                    mma_bf16(bacc[ef * 2], aPh[kb], bh);
                    mma_bf16(bacc[ef * 2], aPh[kb], bl);
                    mma_bf16(bacc[ef * 2], aPl[kb], bh);
                    mma_bf16(bacc[ef * 2 + 1], aPh[kb], bh + 2);
                    mma_bf16(bacc[ef * 2 + 1], aPh[kb], bl + 2);
                    mma_bf16(bacc[ef * 2 + 1], aPl[kb], bh + 2);
                }
            }
        }

        __syncthreads();
        float* XB = (float*)(smc + S_XB);
        const int xbase = ((w >> 1) * 32 + ln) * 68;
        if (w & 1) {
#pragma unroll
            for (int nf = 0; nf < 16; ++nf) {
                XB[xbase + nf * 4 + 0] = bacc[nf][0];
                XB[xbase + nf * 4 + 1] = bacc[nf][1];
                XB[xbase + nf * 4 + 2] = bacc[nf][2];
                XB[xbase + nf * 4 + 3] = bacc[nf][3];
            }
            XB[xbase + 64] = lsum0;
            XB[xbase + 65] = lsum1;
        }
        __syncthreads();
        if (!(w & 1)) {
#pragma unroll
            for (int nf = 0; nf < 16; ++nf) {
                bacc[nf][0] += XB[xbase + nf * 4 + 0];
                bacc[nf][1] += XB[xbase + nf * 4 + 1];
                bacc[nf][2] += XB[xbase + nf * 4 + 2];
                bacc[nf][3] += XB[xbase + nf * 4 + 3];
            }
            lsum0 += XB[xbase + 64];
            lsum1 += XB[xbase + 65];
            lsum0 += __shfl_xor_sync(0xffffffffu, lsum0, 1);
            lsum0 += __shfl_xor_sync(0xffffffffu, lsum0, 2);
            lsum1 += __shfl_xor_sync(0xffffffffu, lsum1, 1);
            lsum1 += __shfl_xor_sync(0xffffffffu, lsum1, 2);
            float li0 = 1.0f / lsum0, li1 = 1.0f / lsum1;
            const int j0 = qb + jw + g;
#pragma unroll
            for (int nf = 0; nf < 16; ++nf) {
                int e0 = h * E + nf * 8 + q2;
                __nv_bfloat162 h01, l01, h23, l23;
                split2(bacc[nf][0] * li0, bacc[nf][1] * li0, h01, l01);
                split2(bacc[nf][2] * li1, bacc[nf][3] * li1, h23, l23);
                size_t b0 = (size_t)j0 * HE + e0;
                size_t b1 = (size_t)(j0 + 8) * HE + e0;
                *(__nv_bfloat162*)&g_bh[b0] = h01;
                *(__nv_bfloat162*)&g_bl[b0] = l01;
                *(__nv_bfloat162*)&g_bh[b1] = h23;
                *(__nv_bfloat162*)&g_bl[b1] = l23;
            }
        }
    }
}

// ---------------------------------------------------------------------------
// gemm_out via mma.sync, cp.async double-buffered k-chunks.
// Per-buffer: Ah 18432 + Al 18432 + Bh 4608 + Bl 4608 = 46080; x2 = 92160.
// ---------------------------------------------------------------------------
#define OBUF 46080
#define O_AH 0
#define O_AL 18432
#define O_BH 36864
#define O_BL 41472
#define OUT_SMEM 92160

__device__ __forceinline__ void prefetch_out(uint32_t sb, int buf, int k0, int bn, int t) {
    const uint32_t ob = sb + buf * OBUF;
#pragma unroll
    for (int r = 0; r < 4; ++r) {
        int id = t + r * 256, row = id >> 3, c8 = id & 7;
        CPA16(ob + O_AH + row * 144 + c8 * 16,
              (const char*)(g_Ah + (size_t)row * HE + k0) + c8 * 16);
        CPA16(ob + O_AL + row * 144 + c8 * 16,
              (const char*)(g_Al + (size_t)row * HE + k0) + c8 * 16);
    }
    {
        int row = t >> 3, c8 = t & 7;
        CPA16(ob + O_BH + row * 144 + c8 * 16,
              (const char*)(g_bh + (size_t)(bn + row) * HE + k0) + c8 * 16);
        CPA16(ob + O_BL + row * 144 + c8 * 16,
              (const char*)(g_bl + (size_t)(bn + row) * HE + k0) + c8 * 16);
    }
    CPA_COMMIT();
}

__global__ __launch_bounds__(256) void gemm_out_tc(float* __restrict__ out) {
    extern __shared__ __align__(128) char sm2[];
    const uint32_t sb = smem_u32(sm2);
    const int t = threadIdx.x, w = t >> 5, ln = t & 31;
    const int bn = blockIdx.x * 32;
    const int mbase = w * 16;
    const int mA = ln >> 3, g8 = ln & 7;
    const int aRow = mbase + g8 + (mA & 1) * 8;
    const int aCol = (mA >> 1) * 8;
    const int bRow = g8 + (mA >> 1) * 8;
    const int bCol = (mA & 1) * 8;

    float acc[4][4];
#pragma unroll
    for (int u = 0; u < 4; u++)
#pragma unroll
        for (int v = 0; v < 4; v++) acc[u][v] = 0.f;

    prefetch_out(sb, 0, 0, bn, t);

    for (int kc = 0; kc < 16; ++kc) {
        __syncthreads();   // prior compute done -> next buffer free
        if (kc < 15) {
            prefetch_out(sb, (kc + 1) & 1, (kc + 1) * 64, bn, t);
            CPA_WAIT(1);
        } else {
            CPA_WAIT(0);
        }
        __syncthreads();   // current buffer visible

        const uint32_t ob = sb + (kc & 1) * OBUF;
#pragma unroll
        for (int kf = 0; kf < 4; ++kf) {
            int ko = kf * 16;
            uint32_t ah[4], al[4];
            uint32_t aoff = (uint32_t)((aRow * 72 + ko + aCol) * 2);
            ldsm4(ah, ob + O_AH + aoff);
            ldsm4(al, ob + O_AL + aoff);
#pragma unroll
            for (int np = 0; np < 2; ++np) {
                int n16 = np * 16;
                uint32_t bh[4], bl[4];
                uint32_t boff = (uint32_t)(((n16 + bRow) * 72 + ko + bCol) * 2);
                ldsm4(bh, ob + O_BH + boff);
                ldsm4(bl, ob + O_BL + boff);
                mma_bf16(acc[np * 2], ah, bh);
                mma_bf16(acc[np * 2], ah, bl);
                mma_bf16(acc[np * 2], al, bh);
                mma_bf16(acc[np * 2 + 1], ah, bh + 2);
                mma_bf16(acc[np * 2 + 1], ah, bl + 2);
                mma_bf16(acc[np * 2 + 1], al, bh + 2);
            }
        }
    }
    const int r0 = mbase + (ln >> 2);
#pragma unroll
    for (int nf = 0; nf < 4; ++nf) {
        int j0 = bn + nf * 8 + (ln & 3) * 2;
        int ee[4] = {r0, r0, r0 + 8, r0 + 8};
        int jj[4] = {j0, j0 + 1, j0, j0 + 1};
#pragma unroll
        for (int q = 0; q < 4; ++q) {
            int dst = (jj[q] < L - 1) ? (E + jj[q] * E + ee[q]) : (2 * E * L + ee[q]);
            out[dst] = acc[nf][q];
        }
    }
}

// ---------------------------------------------------------------------------
extern "C" void kernel_launch(void* const* d_in, const int* in_sizes, int n_in,
                              void* d_out, int out_size) {
    const int* sq = (const int*)d_in[0];
    const int* cq = (const int*)d_in[1];
    const float* ir = (const float*)d_in[2];
    const float* uir = (const float*)d_in[3];
    const float* wr = (const float*)d_in[4];
    const float* Wq = (const float*)d_in[5];
    const float* Wk = (const float*)d_in[6];
    const float* Wv = (const float*)d_in[7];
    const float* Hagg = (const float*)d_in[8];
    float* out = (float*)d_out;
    cudaFuncSetAttribute(attn_kernel, cudaFuncAttributeMaxDynamicSharedMemorySize, ATTN_SMEM);
    cudaFuncSetAttribute(gemm_qkv_tc, cudaFuncAttributeMaxDynamicSharedMemorySize, QKV_SMEM);
    cudaFuncSetAttribute(gemm_out_tc, cudaFuncAttributeMaxDynamicSharedMemorySize, OUT_SMEM);
    build_I_kernel<<<(E * L) / 256, 256>>>(sq, cq, ir, wr, uir, out);
    prep_WA_kernel<<<1024, 256>>>(Wq, Wk, Wv, Hagg);
    gemm_qkv_tc<<<dim3(16, 8, 3), 256, QKV_SMEM>>>();
    attn_kernel<<<dim3(16, H), 256, ATTN_SMEM>>>();
    gemm_out_tc<<<64, 256, OUT_SMEM>>>(out);
}

// round 17
// speedup vs baseline: 1.3172x; 1.2930x over previous
#include <cuda_runtime.h>
#include <cuda_bf16.h>
#include <math.h>
#include <stdint.h>

#define E 128
#define H 8
#define L 2048
#define HE 1024
#define HEL (HE * L)
#define NITEMS 50000
#define WAMT 5
#define SCALE_F 0.08838834764831845f

__device__ __nv_bfloat16 g_Ih[L * E], g_Il[L * E];           // I [l][e]
__device__ __nv_bfloat16 g_Wh[3 * HE * E], g_Wl[3 * HE * E]; // W [z][he][k]
__device__ __nv_bfloat16 g_Qh[H * L * E];                    // [h][l][e], pre-scaled (hi only)
__device__ __nv_bfloat16 g_Kh[H * L * E];                    // [h][l][e] (hi only)
__device__ __nv_bfloat16 g_Vh[H * E * L], g_Vl[H * E * L];   // [h][e][l]
__device__ __nv_bfloat16 g_bh[L * HE], g_bl[L * HE];         // [l][he]
__device__ __nv_bfloat16 g_Ah[E * HE], g_Al[E * HE];         // [e_out][k]

__device__ __forceinline__ uint32_t smem_u32(const void* p) {
    return (uint32_t)__cvta_generic_to_shared(p);
}
__device__ __forceinline__ void ldsm4(uint32_t* r, uint32_t a) {
    asm volatile("ldmatrix.sync.aligned.m8n8.x4.shared.b16 {%0,%1,%2,%3}, [%4];"
                 : "=r"(r[0]), "=r"(r[1]), "=r"(r[2]), "=r"(r[3]) : "r"(a));
}
__device__ __forceinline__ void mma_bf16(float* c, const uint32_t* a, const uint32_t* b) {
    asm volatile("mma.sync.aligned.m16n8k16.row.col.f32.bf16.bf16.f32 "
                 "{%0,%1,%2,%3}, {%4,%5,%6,%7}, {%8,%9}, {%0,%1,%2,%3};"
                 : "+f"(c[0]), "+f"(c[1]), "+f"(c[2]), "+f"(c[3])
                 : "r"(a[0]), "r"(a[1]), "r"(a[2]), "r"(a[3]), "r"(b[0]), "r"(b[1]));
}
__device__ __forceinline__ void split2(float a, float b, __nv_bfloat162& h, __nv_bfloat162& l) {
    h = __floats2bfloat162_rn(a, b);
    float2 r = __bfloat1622float2(h);
    l = __floats2bfloat162_rn(a - r.x, b - r.y);
}
#define CPA16(dst, src) \
    asm volatile("cp.async.cg.shared.global [%0], [%1], 16;" :: "r"(dst), "l"(src) : "memory")
#define CPA_COMMIT() asm volatile("cp.async.commit_group;" ::: "memory")
#define CPA_WAIT(n)  asm volatile("cp.async.wait_group %0;" :: "n"(n) : "memory")

// ---------------------------------------------------------------------------
__global__ void build_I_kernel(const int* __restrict__ sq, const int* __restrict__ cq,
                               const float* __restrict__ ir, const float* __restrict__ wr,
                               const float* __restrict__ uir, float* __restrict__ out) {
    int idx = blockIdx.x * blockDim.x + threadIdx.x;   // idx = l*128 + e
    if (idx < E) out[idx] = uir[idx];
    if (idx >= E * L) return;
    int e = idx & 127, l = idx >> 7;
    float iq = ir[e * NITEMS + sq[l]];
    float val = iq + wr[e * WAMT + cq[l]];
    __nv_bfloat16 hv = __float2bfloat16(val);
    g_Ih[idx] = hv;
    g_Il[idx] = __float2bfloat16(val - __bfloat162float(hv));
    out[E * L + idx] = iq;
}

// Split Wq/Wk/Wv (z=0..2) and Head_agg (z=3) into bf16 hi/lo
__global__ void prep_WA_kernel(const float* __restrict__ Wq, const float* __restrict__ Wk,
                               const float* __restrict__ Wv, const float* __restrict__ A) {
    int idx = blockIdx.x * blockDim.x + threadIdx.x;   // 2 floats each
    int z = idx >> 16;
    int off = (idx & 65535) * 2;
    const float* S = (z == 0) ? Wq : (z == 1 ? Wk : (z == 2 ? Wv : A));
    __nv_bfloat16* Dh = (z < 3) ? (g_Wh + (size_t)z * (HE * E)) : g_Ah;
    __nv_bfloat16* Dl = (z < 3) ? (g_Wl + (size_t)z * (HE * E)) : g_Al;
    float2 f = *(const float2*)&S[off];
    __nv_bfloat162 hh, ll;
    split2(f.x, f.y, hh, ll);
    *(__nv_bfloat162*)&Dh[off] = hh;
    *(__nv_bfloat162*)&Dl[off] = ll;
}

// ---------------------------------------------------------------------------
// QKV projection. Grid (16,8,3). Per CTA: M=128 he, N=128 l, K=128.
// Warp grid 2m x 4n. z<2 (Q/K): 1-term (hi x hi), hi-only output.
// z=2 (V): 3-term compensated, hi/lo output.
// ---------------------------------------------------------------------------
#define QSTR 136
#define QA_H 0
#define QA_L 34816
#define QB_H 69632
#define QB_L 104448
#define QKV_SMEM 139264

__global__ __launch_bounds__(256) void gemm_qkv_tc() {
    extern __shared__ __align__(128) char smq[];
    const uint32_t sb = smem_u32(smq);
    const int t = threadIdx.x, w = t >> 5, ln = t & 31;
    const int z = blockIdx.z;
    const int bm = blockIdx.y * 128;   // he tile
    const int bn = blockIdx.x * 128;   // l tile
    const __nv_bfloat16* Wh = g_Wh + (size_t)z * (HE * E);
    const __nv_bfloat16* Wl = g_Wl + (size_t)z * (HE * E);

    // cp.async one-shot loads; lo tiles only needed for z==2
#pragma unroll
    for (int r = 0; r < 8; ++r) {
        int id = t + r * 256, row = id >> 4, c16 = id & 15;
        CPA16(sb + QA_H + row * 272 + c16 * 16,
              (const char*)(Wh + (size_t)(bm + row) * E) + c16 * 16);
        CPA16(sb + QB_H + row * 272 + c16 * 16,
              (const char*)(g_Ih + (size_t)(bn + row) * E) + c16 * 16);
    }
    if (z == 2) {
#pragma unroll
        for (int r = 0; r < 8; ++r) {
            int id = t + r * 256, row = id >> 4, c16 = id & 15;
            CPA16(sb + QA_L + row * 272 + c16 * 16,
                  (const char*)(Wl + (size_t)(bm + row) * E) + c16 * 16);
            CPA16(sb + QB_L + row * 272 + c16 * 16,
                  (const char*)(g_Il + (size_t)(bn + row) * E) + c16 * 16);
        }
    }
    CPA_COMMIT();
    CPA_WAIT(0);
    __syncthreads();

    const int wm = w & 1;              // m-warp: 0..1 (m64 each)
    const int wn = w >> 1;             // n-warp: 0..3 (n32 each)
    const int mA = ln >> 3, g8 = ln & 7;
    const int aRowB = wm * 64 + g8 + (mA & 1) * 8;
    const int aCol  = (mA >> 1) * 8;
    const int bRowB = wn * 32 + g8 + (mA >> 1) * 8;
    const int bCol  = (mA & 1) * 8;

    float acc[16][4];
#pragma unroll
    for (int u = 0; u < 16; u++)
#pragma unroll
        for (int v = 0; v < 4; v++) acc[u][v] = 0.f;

    if (z == 2) {
#pragma unroll
        for (int ks = 0; ks < 8; ++ks) {
            int ko = ks * 16;
            uint32_t ah[4][4], al[4][4];
#pragma unroll
            for (int mt = 0; mt < 4; ++mt) {
                uint32_t aoff = (uint32_t)(((aRowB + mt * 16) * QSTR + ko + aCol) * 2);
                ldsm4(ah[mt], sb + QA_H + aoff);
                ldsm4(al[mt], sb + QA_L + aoff);
            }
#pragma unroll
            for (int nt = 0; nt < 2; ++nt) {
                uint32_t bh[4], bl[4];
                uint32_t boff = (uint32_t)(((bRowB + nt * 16) * QSTR + ko + bCol) * 2);
                ldsm4(bh, sb + QB_H + boff);
                ldsm4(bl, sb + QB_L + boff);
#pragma unroll
                for (int mt = 0; mt < 4; ++mt) {
                    float* c0 = acc[mt * 4 + nt * 2];
                    float* c1 = acc[mt * 4 + nt * 2 + 1];
                    mma_bf16(c0, ah[mt], bh);
                    mma_bf16(c0, ah[mt], bl);
                    mma_bf16(c0, al[mt], bh);
                    mma_bf16(c1, ah[mt], bh + 2);
                    mma_bf16(c1, ah[mt], bl + 2);
                    mma_bf16(c1, al[mt], bh + 2);
                }
            }
        }
    } else {
#pragma unroll
        for (int ks = 0; ks < 8; ++ks) {
            int ko = ks * 16;
            uint32_t ah[4][4];
#pragma unroll
            for (int mt = 0; mt < 4; ++mt) {
                uint32_t aoff = (uint32_t)(((aRowB + mt * 16) * QSTR + ko + aCol) * 2);
                ldsm4(ah[mt], sb + QA_H + aoff);
            }
#pragma unroll
            for (int nt = 0; nt < 2; ++nt) {
                uint32_t bh[4];
                uint32_t boff = (uint32_t)(((bRowB + nt * 16) * QSTR + ko + bCol) * 2);
                ldsm4(bh, sb + QB_H + boff);
#pragma unroll
                for (int mt = 0; mt < 4; ++mt) {
                    mma_bf16(acc[mt * 4 + nt * 2], ah[mt], bh);
                    mma_bf16(acc[mt * 4 + nt * 2 + 1], ah[mt], bh + 2);
                }
            }
        }
    }

    const int g = ln >> 2, q2 = (ln & 3) * 2;
    if (z == 2) {
        // V: direct store [he][l], n (=l) contiguous, hi/lo
#pragma unroll
        for (int mt = 0; mt < 4; ++mt) {
            const int row0 = bm + wm * 64 + mt * 16 + g;
#pragma unroll
            for (int nf = 0; nf < 4; ++nf) {
                const float* cc = acc[mt * 4 + nf];
                int col = bn + wn * 32 + nf * 8 + q2;
                __nv_bfloat162 h01, l01, h23, l23;
                split2(cc[0], cc[1], h01, l01);
                split2(cc[2], cc[3], h23, l23);
                *(__nv_bfloat162*)&g_Vh[(size_t)row0 * L + col] = h01;
                *(__nv_bfloat162*)&g_Vl[(size_t)row0 * L + col] = l01;
                *(__nv_bfloat162*)&g_Vh[(size_t)(row0 + 8) * L + col] = h23;
                *(__nv_bfloat162*)&g_Vl[(size_t)(row0 + 8) * L + col] = l23;
            }
        }
    } else {
        // Q/K: transpose via fp32 staging aliased onto B region, hi-only [h][l][e]
        __syncthreads();
        float* st = (float*)(smq + QB_H);   // [128 l][132]
#pragma unroll
        for (int mt = 0; mt < 4; ++mt) {
            const int r0 = wm * 64 + mt * 16 + g;
#pragma unroll
            for (int nf = 0; nf < 4; ++nf) {
                const float* cc = acc[mt * 4 + nf];
                int lc = wn * 32 + nf * 8 + q2;
                st[lc * 132 + r0]           = cc[0];
                st[(lc + 1) * 132 + r0]     = cc[1];
                st[lc * 132 + r0 + 8]       = cc[2];
                st[(lc + 1) * 132 + r0 + 8] = cc[3];
            }
        }
        __syncthreads();
        const float s = (z == 0) ? SCALE_F : 1.0f;
        __nv_bfloat16* Dh = (z == 0) ? g_Qh : g_Kh;
        const int lrow = t >> 1, ec = (t & 1) * 64;
        const int h = bm >> 7;
        size_t base = ((size_t)h * L + bn + lrow) * E + ec;
#pragma unroll
        for (int i4 = 0; i4 < 16; ++i4) {
            float4 f = *(const float4*)&st[lrow * 132 + ec + i4 * 4];
            *(__nv_bfloat162*)&Dh[base + i4 * 4] =
                __floats2bfloat162_rn(f.x * s, f.y * s);
            *(__nv_bfloat162*)&Dh[base + i4 * 4 + 2] =
                __floats2bfloat162_rn(f.z * s, f.w * s);
        }
    }
}

// ---------------------------------------------------------------------------
// Flash attention, register-resident P. S-phase single-term (Qh x Kh).
// PV 3-term (P hi/lo x V hi/lo). Q/K hi-only smem.
// ---------------------------------------------------------------------------
#define SQK 136
#define SV 72
#define S_QH 0
#define S_KV 17408
#define KSZ  17408
#define VSZ  18432
#define BUFSZ (KSZ + 2 * VSZ)          /* 54272 */
#define S_XB (S_KV + BUFSZ)
#define ATTN_SMEM (S_KV + 2 * BUFSZ)   /* 125952 */

__device__ __forceinline__ void prefetch_kv(uint32_t sb, int buf,
                                            const __nv_bfloat16* Kh,
                                            const __nv_bfloat16* Vh, const __nv_bfloat16* Vl,
                                            int ib, int t) {
    const uint32_t kb = sb + S_KV + buf * BUFSZ;
#pragma unroll
    for (int r = 0; r < 4; ++r) {
        int id = t + r * 256, row = id >> 4, c16 = id & 15;
        CPA16(kb + row * 272 + c16 * 16,
              (const char*)(Kh + (size_t)(ib * 64 + row) * E) + c16 * 16);
    }
    const uint32_t vb = kb + KSZ;
#pragma unroll
    for (int r = 0; r < 4; ++r) {
        int id = t + r * 256, row = id >> 3, c8 = id & 7;
        CPA16(vb + row * 144 + c8 * 16,
              (const char*)(Vh + (size_t)row * L + ib * 64) + c8 * 16);
        CPA16(vb + VSZ + row * 144 + c8 * 16,
              (const char*)(Vl + (size_t)row * L + ib * 64) + c8 * 16);
    }
    CPA_COMMIT();
}

__global__ __launch_bounds__(256, 1) void attn_kernel() {
    extern __shared__ __align__(128) char smc[];
    const uint32_t sb = smem_u32(smc);
    const int t = threadIdx.x, w = t >> 5, ln = t & 31;
    const int h = blockIdx.y, px = blockIdx.x;

    const __nv_bfloat16* Qh = g_Qh + (size_t)h * L * E;
    const __nv_bfloat16* Kh = g_Kh + (size_t)h * L * E;
    const __nv_bfloat16* Vh = g_Vh + (size_t)h * E * L;
    const __nv_bfloat16* Vl = g_Vl + (size_t)h * E * L;

    const int jw  = (w >> 1) * 16;
    const int ihw = (w & 1) * 32;
    const int g   = ln >> 2;
    const int q2  = (ln & 3) * 2;
    const int mA = ln >> 3, g8 = ln & 7;
    const int aRow = jw + g8 + (mA & 1) * 8;
    const int aCol = (mA >> 1) * 8;
    const int bRow = g8 + (mA >> 1) * 8;
    const int bCol = (mA & 1) * 8;

#pragma unroll 1
    for (int ts = 0; ts < 2; ++ts) {
        const int jt = ts ? px : (31 - px);
        const int qb = jt << 6;
        __syncthreads();   // prior tile fully done

        prefetch_kv(sb, 0, Kh, Vh, Vl, 0, t);

        // Q tile copy (hi only): 64 rows x 16 uint4
#pragma unroll
        for (int r = 0; r < 4; ++r) {
            int id = t + r * 256, row = id >> 4, c16 = id & 15;
            *(uint4*)(smc + S_QH + row * 272 + c16 * 16) =
                *((const uint4*)(Qh + (size_t)(qb + row) * E) + c16);
        }

        float bacc[16][4];
#pragma unroll
        for (int u = 0; u < 16; u++)
#pragma unroll
            for (int v = 0; v < 4; v++) bacc[u][v] = 0.f;
        float lsum0 = 0.f, lsum1 = 0.f;
        const int jg0 = qb + jw + g, jg1 = jg0 + 8;

#pragma unroll 1
        for (int ib = 0; ib <= jt; ++ib) {
            __syncthreads();
            if (ib < jt) {
                prefetch_kv(sb, (ib + 1) & 1, Kh, Vh, Vl, ib + 1, t);
                CPA_WAIT(1);
            } else {
                CPA_WAIT(0);
            }
            __syncthreads();

            const uint32_t kH = sb + S_KV + (ib & 1) * BUFSZ;
            const uint32_t vH = kH + KSZ;
            const uint32_t vL = vH + VSZ;

            // ---- S[j16][i32] = Qh x Kh (single term) ----
            float sacc[4][4];
#pragma unroll
            for (int u = 0; u < 4; u++)
#pragma unroll
                for (int v = 0; v < 4; v++) sacc[u][v] = 0.f;
#pragma unroll
            for (int ks = 0; ks < 8; ++ks) {
                int e0 = ks * 16;
                uint32_t ah[4];
                ldsm4(ah, sb + S_QH + (uint32_t)((aRow * SQK + e0 + aCol) * 2));
#pragma unroll
                for (int it = 0; it < 2; ++it) {
                    uint32_t bh[4];
                    uint32_t boff = (uint32_t)(((ihw + it * 16 + bRow) * SQK + e0 + bCol) * 2);
                    ldsm4(bh, kH + boff);
                    mma_bf16(sacc[it * 2], ah, bh);
                    mma_bf16(sacc[it * 2 + 1], ah, bh + 2);
                }
            }

            // ---- exp + mask + pack P into A fragments (registers only) ----
            uint32_t aPh[2][4], aPl[2][4];
#pragma unroll
            for (int nf = 0; nf < 4; ++nf) {
                int ig = ib * 64 + ihw + nf * 8 + q2;
                float p0 = (ig     <= jg0) ? __expf(sacc[nf][0]) : 0.f;
                float p1 = (ig + 1 <= jg0) ? __expf(sacc[nf][1]) : 0.f;
                float p2 = (ig     <= jg1) ? __expf(sacc[nf][2]) : 0.f;
                float p3 = (ig + 1 <= jg1) ? __expf(sacc[nf][3]) : 0.f;
                lsum0 += p0 + p1;
                lsum1 += p2 + p3;
                __nv_bfloat162 h01, l01, h23, l23;
                split2(p0, p1, h01, l01);
                split2(p2, p3, h23, l23);
                int kb = nf >> 1, sub = (nf & 1) * 2;
                aPh[kb][sub]     = *(uint32_t*)&h01;
                aPh[kb][sub + 1] = *(uint32_t*)&h23;
                aPl[kb][sub]     = *(uint32_t*)&l01;
                aPl[kb][sub + 1] = *(uint32_t*)&l23;
            }

            // ---- PV: b[j16][e128] += P x V, 3-term ----
#pragma unroll
            for (int kb = 0; kb < 2; ++kb) {
#pragma unroll
                for (int ef = 0; ef < 8; ++ef) {
                    uint32_t bh[4], bl[4];
                    uint32_t boff = (uint32_t)(((ef * 16 + bRow) * SV +
                                                ihw + kb * 16 + bCol) * 2);
                    ldsm4(bh, vH + boff);
                    ldsm4(bl, vL + boff);
                    mma_bf16(bacc[ef * 2], aPh[kb], bh);
                    mma_bf16(bacc[ef * 2], aPh[kb], bl);
                    mma_bf16(bacc[ef * 2], aPl[kb], bh);
                    mma_bf16(bacc[ef * 2 + 1], aPh[kb], bh + 2);
                    mma_bf16(bacc[ef * 2 + 1], aPh[kb], bl + 2);
                    mma_bf16(bacc[ef * 2 + 1], aPl[kb], bh + 2);
                }
            }
        }

        // ---- tile end: combine warp pairs, normalize, store ----
        __syncthreads();   // all PV reads done (XB aliases buffer 1)
        float* XB = (float*)(smc + S_XB);
        const int xbase = ((w >> 1) * 32 + ln) * 68;
        if (w & 1) {
#pragma unroll
            for (int nf = 0; nf < 16; ++nf) {
                XB[xbase + nf * 4 + 0] = bacc[nf][0];
                XB[xbase + nf * 4 + 1] = bacc[nf][1];
                XB[xbase + nf * 4 + 2] = bacc[nf][2];
                XB[xbase + nf * 4 + 3] = bacc[nf][3];
            }
            XB[xbase + 64] = lsum0;
            XB[xbase + 65] = lsum1;
        }
        __syncthreads();
        if (!(w & 1)) {
#pragma unroll
            for (int nf = 0; nf < 16; ++nf) {
                bacc[nf][0] += XB[xbase + nf * 4 + 0];
                bacc[nf][1] += XB[xbase + nf * 4 + 1];
                bacc[nf][2] += XB[xbase + nf * 4 + 2];
                bacc[nf][3] += XB[xbase + nf * 4 + 3];
            }
            lsum0 += XB[xbase + 64];
            lsum1 += XB[xbase + 65];
            lsum0 += __shfl_xor_sync(0xffffffffu, lsum0, 1);
            lsum0 += __shfl_xor_sync(0xffffffffu, lsum0, 2);
            lsum1 += __shfl_xor_sync(0xffffffffu, lsum1, 1);
            lsum1 += __shfl_xor_sync(0xffffffffu, lsum1, 2);
            float li0 = 1.0f / lsum0, li1 = 1.0f / lsum1;
            const int j0 = qb + jw + g;
#pragma unroll
            for (int nf = 0; nf < 16; ++nf) {
                int e0 = h * E + nf * 8 + q2;
                __nv_bfloat162 h01, l01, h23, l23;
                split2(bacc[nf][0] * li0, bacc[nf][1] * li0, h01, l01);
                split2(bacc[nf][2] * li1, bacc[nf][3] * li1, h23, l23);
                size_t b0 = (size_t)j0 * HE + e0;
                size_t b1 = (size_t)(j0 + 8) * HE + e0;
                *(__nv_bfloat162*)&g_bh[b0] = h01;
                *(__nv_bfloat162*)&g_bl[b0] = l01;
                *(__nv_bfloat162*)&g_bh[b1] = h23;
                *(__nv_bfloat162*)&g_bl[b1] = l23;
            }
        }
    }
}

// ---------------------------------------------------------------------------
// gemm_out via mma.sync, cp.async double-buffered k-chunks. 3-term.
// ---------------------------------------------------------------------------
#define OBUF 46080
#define O_AH 0
#define O_AL 18432
#define O_BH 36864
#define O_BL 41472
#define OUT_SMEM 92160

__device__ __forceinline__ void prefetch_out(uint32_t sb, int buf, int k0, int bn, int t) {
    const uint32_t ob = sb + buf * OBUF;
#pragma unroll
    for (int r = 0; r < 4; ++r) {
        int id = t + r * 256, row = id >> 3, c8 = id & 7;
        CPA16(ob + O_AH + row * 144 + c8 * 16,
              (const char*)(g_Ah + (size_t)row * HE + k0) + c8 * 16);
        CPA16(ob + O_AL + row * 144 + c8 * 16,
              (const char*)(g_Al + (size_t)row * HE + k0) + c8 * 16);
    }
    {
        int row = t >> 3, c8 = t & 7;
        CPA16(ob + O_BH + row * 144 + c8 * 16,
              (const char*)(g_bh + (size_t)(bn + row) * HE + k0) + c8 * 16);
        CPA16(ob + O_BL + row * 144 + c8 * 16,
              (const char*)(g_bl + (size_t)(bn + row) * HE + k0) + c8 * 16);
    }
    CPA_COMMIT();
}

__global__ __launch_bounds__(256) void gemm_out_tc(float* __restrict__ out) {
    extern __shared__ __align__(128) char sm2[];
    const uint32_t sb = smem_u32(sm2);
    const int t = threadIdx.x, w = t >> 5, ln = t & 31;
    const int bn = blockIdx.x * 32;
    const int mbase = w * 16;
    const int mA = ln >> 3, g8 = ln & 7;
    const int aRow = mbase + g8 + (mA & 1) * 8;
    const int aCol = (mA >> 1) * 8;
    const int bRow = g8 + (mA >> 1) * 8;
    const int bCol = (mA & 1) * 8;

    float acc[4][4];
#pragma unroll
    for (int u = 0; u < 4; u++)
#pragma unroll
        for (int v = 0; v < 4; v++) acc[u][v] = 0.f;

    prefetch_out(sb, 0, 0, bn, t);

    for (int kc = 0; kc < 16; ++kc) {
        __syncthreads();
        if (kc < 15) {
            prefetch_out(sb, (kc + 1) & 1, (kc + 1) * 64, bn, t);
            CPA_WAIT(1);
        } else {
            CPA_WAIT(0);
        }
        __syncthreads();

        const uint32_t ob = sb + (kc & 1) * OBUF;
#pragma unroll
        for (int kf = 0; kf < 4; ++kf) {
            int ko = kf * 16;
            uint32_t ah[4], al[4];
            uint32_t aoff = (uint32_t)((aRow * 72 + ko + aCol) * 2);
            ldsm4(ah, ob + O_AH + aoff);
            ldsm4(al, ob + O_AL + aoff);
#pragma unroll
            for (int np = 0; np < 2; ++np) {
                int n16 = np * 16;
                uint32_t bh[4], bl[4];
                uint32_t boff = (uint32_t)(((n16 + bRow) * 72 + ko + bCol) * 2);
                ldsm4(bh, ob + O_BH + boff);
                ldsm4(bl, ob + O_BL + boff);
                mma_bf16(acc[np * 2], ah, bh);
                mma_bf16(acc[np * 2], ah, bl);
                mma_bf16(acc[np * 2], al, bh);
                mma_bf16(acc[np * 2 + 1], ah, bh + 2);
                mma_bf16(acc[np * 2 + 1], ah, bl + 2);
                mma_bf16(acc[np * 2 + 1], al, bh + 2);
            }
        }
    }
    const int r0 = mbase + (ln >> 2);
#pragma unroll
    for (int nf = 0; nf < 4; ++nf) {
        int j0 = bn + nf * 8 + (ln & 3) * 2;
        int ee[4] = {r0, r0, r0 + 8, r0 + 8};
        int jj[4] = {j0, j0 + 1, j0, j0 + 1};
#pragma unroll
        for (int q = 0; q < 4; ++q) {
            int dst = (jj[q] < L - 1) ? (E + jj[q] * E + ee[q]) : (2 * E * L + ee[q]);
            out[dst] = acc[nf][q];
        }
    }
}

// ---------------------------------------------------------------------------
extern "C" void kernel_launch(void* const* d_in, const int* in_sizes, int n_in,
                              void* d_out, int out_size) {
    const int* sq = (const int*)d_in[0];
    const int* cq = (const int*)d_in[1];
    const float* ir = (const float*)d_in[2];
    const float* uir = (const float*)d_in[3];
    const float* wr = (const float*)d_in[4];
    const float* Wq = (const float*)d_in[5];
    const float* Wk = (const float*)d_in[6];
    const float* Wv = (const float*)d_in[7];
    const float* Hagg = (const float*)d_in[8];
    float* out = (float*)d_out;
    cudaFuncSetAttribute(attn_kernel, cudaFuncAttributeMaxDynamicSharedMemorySize, ATTN_SMEM);
    cudaFuncSetAttribute(gemm_qkv_tc, cudaFuncAttributeMaxDynamicSharedMemorySize, QKV_SMEM);
    cudaFuncSetAttribute(gemm_out_tc, cudaFuncAttributeMaxDynamicSharedMemorySize, OUT_SMEM);
    build_I_kernel<<<(E * L) / 256, 256>>>(sq, cq, ir, wr, uir, out);
    prep_WA_kernel<<<1024, 256>>>(Wq, Wk, Wv, Hagg);
    gemm_qkv_tc<<<dim3(16, 8, 3), 256, QKV_SMEM>>>();
    attn_kernel<<<dim3(16, H), 256, ATTN_SMEM>>>();
    gemm_out_tc<<<64, 256, OUT_SMEM>>>(out);
}